// round 16
// baseline (speedup 1.0000x reference)
#include <cuda_runtime.h>
#include <cuda_bf16.h>
#include <cstdint>

// ---------------- problem constants ----------------
#define B_SZ     2048
#define D_SZ     128
#define C_SZ     64
#define T_STEPS  300
#define HU       100
#define ROWS_TOTAL (B_SZ * T_STEPS)       // 614400
#define GRID     148
#define NTH      512
#define NCHUNK   (ROWS_TOTAL / 16)        // 38400

#define KP      112                        // padded hidden; col/row 100 = bias lane
#define BIAS_K  100
#define W23_LD  120
#define W4_LD   136
#define W2_OFF  0
#define W3_OFF  (KP * W23_LD)
#define W4_OFF  (2 * KP * W23_LD)
#define W_TOTAL (2 * KP * W23_LD + KP * W4_LD)   // 42112 b16
#define SMEM_MAIN (W_TOTAL * 2)                  // 84224 B

// prep packed-weight layouts (bf16, [k][LD])
#define PBLD   216
#define P3LD   72
#define PULD   120
#define W1P_N  (128 * PBLD)
#define W2P_N  (208 * PBLD)
#define W3P_N  (208 * P3LD)
#define U1PP_N (128 * PULD)
#define U1QP_N (64 * PULD)
#define PREP_SMEM ((W2P_N + 2 * 16 * PBLD) * 2)
#define PTH    256

// ---------------- device globals ----------------
__device__ __align__(16) __nv_bfloat16 g_Pb[B_SZ * KP];
__device__ __align__(16) __nv_bfloat16 g_Qb[B_SZ * KP];
__device__ float g_F[B_SZ];
__device__ unsigned int g_done;
__device__ unsigned int g_work;
__device__ __align__(16) uint16_t g_W1p[W1P_N];
__device__ __align__(16) uint16_t g_W2p[W2P_N];
__device__ __align__(16) uint16_t g_W3p[W3P_N];
__device__ __align__(16) uint16_t g_U1Pp[U1PP_N];
__device__ __align__(16) uint16_t g_U1Qp[U1QP_N];

// ---------------- helpers ----------------
__device__ __forceinline__ uint32_t smem_u32(const void* p) {
    return (uint32_t)__cvta_generic_to_shared(p);
}
__device__ __forceinline__ void ldm_x4_t(uint32_t addr, uint32_t& r0, uint32_t& r1,
                                         uint32_t& r2, uint32_t& r3) {
    asm volatile("ldmatrix.sync.aligned.m8n8.x4.trans.shared.b16 {%0,%1,%2,%3}, [%4];"
                 : "=r"(r0), "=r"(r1), "=r"(r2), "=r"(r3) : "r"(addr));
}
__device__ __forceinline__ void mma_bf16(float c[4], uint32_t a0, uint32_t a1, uint32_t a2,
                                         uint32_t a3, uint32_t b0, uint32_t b1) {
    asm volatile(
        "mma.sync.aligned.m16n8k16.row.col.f32.bf16.bf16.f32 "
        "{%0,%1,%2,%3},{%4,%5,%6,%7},{%8,%9},{%0,%1,%2,%3};"
        : "+f"(c[0]), "+f"(c[1]), "+f"(c[2]), "+f"(c[3])
        : "r"(a0), "r"(a1), "r"(a2), "r"(a3), "r"(b0), "r"(b1));
}
__device__ __forceinline__ uint32_t pack_relu2(float v0, float v1) {
    __nv_bfloat162 h = __floats2bfloat162_rn(fmaxf(v0, 0.f), fmaxf(v1, 0.f));
    return *(uint32_t*)&h;
}
__device__ __forceinline__ uint32_t pack2(float v0, float v1) {
    __nv_bfloat162 h = __floats2bfloat162_rn(v0, v1);
    return *(uint32_t*)&h;
}
__device__ __forceinline__ uint32_t bpair(const uint16_t* P, const uint16_t* Q,
                                          int k, float tv) {
    uint32_t pu = __ldg((const uint32_t*)(P + k));
    uint32_t qu = __ldg((const uint32_t*)(Q + k));
    float2 p2 = __bfloat1622float2(*(__nv_bfloat162*)&pu);
    float2 q2 = __bfloat1622float2(*(__nv_bfloat162*)&qu);
    return pack2(fmaxf(fmaf(tv, p2.x, q2.x), 0.f), fmaxf(fmaf(tv, p2.y, q2.y), 0.f));
}

// 13-tile chained GEMM (cols 0..103): 6 full tile-pairs + half pair (acc[12] only).
template<int BLD>
__device__ __forceinline__ void gemm_chain13(const uint32_t af[7][4], const uint16_t* wS,
                                             int l16, int lh, float acc[13][4])
{
    #pragma unroll
    for (int nt = 0; nt < 13; nt++)
        #pragma unroll
        for (int i = 0; i < 4; i++) acc[nt][i] = 0.f;
    #pragma unroll
    for (int kk = 0; kk < 7; kk++) {
        const uint16_t* wrow = wS + (kk * 16 + l16) * BLD + 8 * lh;
        #pragma unroll
        for (int np = 0; np < 6; np++) {
            uint32_t r0, r1, r2, r3;
            ldm_x4_t(smem_u32(wrow + np * 16), r0, r1, r2, r3);
            mma_bf16(acc[2 * np],     af[kk][0], af[kk][1], af[kk][2], af[kk][3], r0, r1);
            mma_bf16(acc[2 * np + 1], af[kk][0], af[kk][1], af[kk][2], af[kk][3], r2, r3);
        }
        {
            uint32_t r0, r1, r2, r3;
            ldm_x4_t(smem_u32(wrow + 6 * 16), r0, r1, r2, r3);
            mma_bf16(acc[12], af[kk][0], af[kk][1], af[kk][2], af[kk][3], r0, r1);
        }
    }
}
template<int BLD>
__device__ __forceinline__ void gemm_chain16(const uint32_t af[7][4], const uint16_t* wS,
                                             int l16, int lh, float acc[16][4])
{
    #pragma unroll
    for (int nt = 0; nt < 16; nt++)
        #pragma unroll
        for (int i = 0; i < 4; i++) acc[nt][i] = 0.f;
    #pragma unroll
    for (int kk = 0; kk < 7; kk++) {
        const uint16_t* wrow = wS + (kk * 16 + l16) * BLD + 8 * lh;
        #pragma unroll
        for (int np = 0; np < 8; np++) {
            uint32_t r0, r1, r2, r3;
            ldm_x4_t(smem_u32(wrow + np * 16), r0, r1, r2, r3);
            mma_bf16(acc[2 * np],     af[kk][0], af[kk][1], af[kk][2], af[kk][3], r0, r1);
            mma_bf16(acc[2 * np + 1], af[kk][0], af[kk][1], af[kk][2], af[kk][3], r2, r3);
        }
    }
}
__device__ __forceinline__ void repack13(const float acc[13][4], uint32_t af[7][4])
{
    #pragma unroll
    for (int j = 0; j < 6; j++) {
        af[j][0] = pack_relu2(acc[2 * j][0],     acc[2 * j][1]);
        af[j][1] = pack_relu2(acc[2 * j][2],     acc[2 * j][3]);
        af[j][2] = pack_relu2(acc[2 * j + 1][0], acc[2 * j + 1][1]);
        af[j][3] = pack_relu2(acc[2 * j + 1][2], acc[2 * j + 1][3]);
    }
    af[6][0] = pack_relu2(acc[12][0], acc[12][1]);
    af[6][1] = pack_relu2(acc[12][2], acc[12][3]);
    af[6][2] = 0u;
    af[6][3] = 0u;
}

// ---------------- pack: pad prep weights + zero F + reset tickets ----------------
__global__ void pack_prep(const float* __restrict__ W1, const float* __restrict__ W2,
                          const float* __restrict__ W3, const float* __restrict__ U1)
{
    int i = blockIdx.x * blockDim.x + threadIdx.x;
    int which = blockIdx.y;
    if (which == 0) {
        if (i < W1P_N) {
            int k = i / PBLD, n = i - k * PBLD;
            float v = (k < 128 && n < 200) ? __ldg(W1 + k * 200 + n) : 0.f;
            __nv_bfloat16 h = __float2bfloat16(v);
            g_W1p[i] = *(uint16_t*)&h;
        }
    } else if (which == 1) {
        if (i < W2P_N) {
            int k = i / PBLD, n = i - k * PBLD;
            float v = (k < 200 && n < 200) ? __ldg(W2 + k * 200 + n) : 0.f;
            __nv_bfloat16 h = __float2bfloat16(v);
            g_W2p[i] = *(uint16_t*)&h;
        }
    } else if (which == 2) {
        if (i < W3P_N) {
            int k = i / P3LD, n = i - k * P3LD;
            float v = (k < 200 && n < C_SZ) ? __ldg(W3 + k * C_SZ + n) : 0.f;
            __nv_bfloat16 h = __float2bfloat16(v);
            g_W3p[i] = *(uint16_t*)&h;
        }
    } else if (which == 3) {
        if (i < U1PP_N) {
            int k = i / PULD, n = i - k * PULD;
            float v = (k < 128 && n < HU) ? __ldg(U1 + k * HU + n) : 0.f;
            __nv_bfloat16 h = __float2bfloat16(v);
            g_U1Pp[i] = *(uint16_t*)&h;
        }
    } else if (which == 4) {
        if (i < U1QP_N) {
            int k = i / PULD, n = i - k * PULD;
            float v = (k < 64 && n < HU) ? __ldg(U1 + (D_SZ + k) * HU + n) : 0.f;
            __nv_bfloat16 h = __float2bfloat16(v);
            g_U1Qp[i] = *(uint16_t*)&h;
        }
    } else {
        if (i < B_SZ) g_F[i] = 0.f;
        if (i == 0) { g_done = 0u; g_work = 0u; }
    }
}

// ---------------- prep v8: tensor-core prep, 128 CTAs x 16 rows x 256 thr ---------
__device__ __forceinline__ void cpy16(const uint16_t* g, uint16_t* s, int n16, int tid) {
    const uint4* src = (const uint4*)g;
    uint4* dst = (uint4*)s;
    for (int i = tid; i < n16 / 8; i += PTH) dst[i] = src[i];
}

template<int K16>
__device__ __forceinline__ void layer_mma(const uint32_t af[][4], const uint16_t* wS,
                                          int BLD, int npairs, int nw, int l16, int lh,
                                          int tg, int qrow, const float* bias, int nreal,
                                          uint16_t* outAct, int outLD)
{
    for (int p = nw; p < npairs; p += 8) {
        float acc[2][4] = {};
        #pragma unroll
        for (int kk = 0; kk < K16; kk++) {
            uint32_t r0, r1, r2, r3;
            ldm_x4_t(smem_u32(wS + (kk * 16 + l16) * BLD + p * 16 + 8 * lh),
                     r0, r1, r2, r3);
            mma_bf16(acc[0], af[kk][0], af[kk][1], af[kk][2], af[kk][3], r0, r1);
            mma_bf16(acc[1], af[kk][0], af[kk][1], af[kk][2], af[kk][3], r2, r3);
        }
        #pragma unroll
        for (int t = 0; t < 2; t++) {
            int c = p * 16 + t * 8 + tg * 2;
            float b0 = (c < nreal)     ? __ldg(bias + c)     : 0.f;
            float b1 = (c + 1 < nreal) ? __ldg(bias + c + 1) : 0.f;
            *(uint32_t*)(outAct + qrow * outLD + c) =
                pack_relu2(acc[t][0] + b0, acc[t][1] + b1);
            *(uint32_t*)(outAct + (qrow + 8) * outLD + c) =
                pack_relu2(acc[t][2] + b0, acc[t][3] + b1);
        }
    }
}

template<int K16>
__device__ __forceinline__ void build_af(uint32_t af[][4], const uint16_t* act,
                                         int LD, int tg, int qrow)
{
    #pragma unroll
    for (int j = 0; j < K16; j++) {
        int k0 = j * 16 + tg * 2;
        af[j][0] = *(const uint32_t*)(act + qrow * LD + k0);
        af[j][1] = *(const uint32_t*)(act + (qrow + 8) * LD + k0);
        af[j][2] = *(const uint32_t*)(act + qrow * LD + k0 + 8);
        af[j][3] = *(const uint32_t*)(act + (qrow + 8) * LD + k0 + 8);
    }
}

__global__ void __launch_bounds__(PTH, 1)
prep_tensor(const float* __restrict__ x,
            const float* __restrict__ b1, const float* __restrict__ b2,
            const float* __restrict__ b3, const float* __restrict__ c1)
{
    extern __shared__ __align__(16) uint16_t ps[];
    uint16_t* Wbuf = ps;
    uint16_t* act1 = ps + W2P_N;
    uint16_t* act2 = act1 + 16 * PBLD;

    int tid = threadIdx.x;
    int lane = tid & 31, nw = tid >> 5;      // 8 warps
    int tg = lane & 3, qrow = lane >> 2;
    int l16 = lane & 15, lh = lane >> 4;
    int m0 = blockIdx.x * 16;

    cpy16(g_W1p, Wbuf, W1P_N, tid);
    __syncthreads();

    uint32_t afx[8][4];
    {
        const float* xA = x + (m0 + qrow) * D_SZ;
        const float* xB = xA + 8 * D_SZ;
        #pragma unroll
        for (int j = 0; j < 8; j++) {
            int k0 = j * 16 + tg * 2;
            float2 a0 = *(const float2*)(xA + k0);
            float2 a1 = *(const float2*)(xB + k0);
            float2 a2 = *(const float2*)(xA + k0 + 8);
            float2 a3 = *(const float2*)(xB + k0 + 8);
            afx[j][0] = pack2(a0.x, a0.y);
            afx[j][1] = pack2(a1.x, a1.y);
            afx[j][2] = pack2(a2.x, a2.y);
            afx[j][3] = pack2(a3.x, a3.y);
        }
    }
    layer_mma<8>(afx, Wbuf, PBLD, 13, nw, l16, lh, tg, qrow, b1, 200, act1, PBLD);
    __syncthreads();

    cpy16(g_W2p, Wbuf, W2P_N, tid);
    __syncthreads();
    uint32_t af2[13][4];
    build_af<13>(af2, act1, PBLD, tg, qrow);
    layer_mma<13>(af2, Wbuf, PBLD, 13, nw, l16, lh, tg, qrow, b2, 200, act2, PBLD);
    __syncthreads();

    cpy16(g_W3p,  Wbuf,                  W3P_N,  tid);
    cpy16(g_U1Pp, Wbuf + W3P_N,          U1PP_N, tid);
    cpy16(g_U1Qp, Wbuf + W3P_N + U1PP_N, U1QP_N, tid);
    __syncthreads();

    uint32_t af3[13][4];
    build_af<13>(af3, act2, PBLD, tg, qrow);
    layer_mma<13>(af3, Wbuf, P3LD, 4, nw, l16, lh, tg, qrow, b3, C_SZ, act1, PBLD);

    {
        const uint16_t* Up = Wbuf + W3P_N;
        for (int p = nw; p < 7; p += 8) {
            float acc[2][4] = {};
            #pragma unroll
            for (int kk = 0; kk < 8; kk++) {
                uint32_t r0, r1, r2, r3;
                ldm_x4_t(smem_u32(Up + (kk * 16 + l16) * PULD + p * 16 + 8 * lh),
                         r0, r1, r2, r3);
                mma_bf16(acc[0], afx[kk][0], afx[kk][1], afx[kk][2], afx[kk][3], r0, r1);
                mma_bf16(acc[1], afx[kk][0], afx[kk][1], afx[kk][2], afx[kk][3], r2, r3);
            }
            #pragma unroll
            for (int t = 0; t < 2; t++) {
                int c = p * 16 + t * 8 + tg * 2;
                *(uint32_t*)((uint16_t*)g_Pb + (m0 + qrow) * KP + c) =
                    pack2(acc[t][0], acc[t][1]);
                *(uint32_t*)((uint16_t*)g_Pb + (m0 + qrow + 8) * KP + c) =
                    pack2(acc[t][2], acc[t][3]);
            }
        }
    }
    __syncthreads();

    {
        const uint16_t* Uq = Wbuf + W3P_N + U1PP_N;
        uint32_t afq[4][4];
        build_af<4>(afq, act1, PBLD, tg, qrow);
        for (int p = nw; p < 7; p += 8) {
            float acc[2][4] = {};
            #pragma unroll
            for (int kk = 0; kk < 4; kk++) {
                uint32_t r0, r1, r2, r3;
                ldm_x4_t(smem_u32(Uq + (kk * 16 + l16) * PULD + p * 16 + 8 * lh),
                         r0, r1, r2, r3);
                mma_bf16(acc[0], afq[kk][0], afq[kk][1], afq[kk][2], afq[kk][3], r0, r1);
                mma_bf16(acc[1], afq[kk][0], afq[kk][1], afq[kk][2], afq[kk][3], r2, r3);
            }
            #pragma unroll
            for (int t = 0; t < 2; t++) {
                int c = p * 16 + t * 8 + tg * 2;
                float q0 = (c < HU) ? __ldg(c1 + c)
                                    : ((c == BIAS_K) ? 1.0f : 0.f);
                float q1 = (c + 1 < HU) ? __ldg(c1 + c + 1)
                                        : ((c + 1 == BIAS_K) ? 1.0f : 0.f);
                *(uint32_t*)((uint16_t*)g_Qb + (m0 + qrow) * KP + c) =
                    pack2(acc[t][0] + q0, acc[t][1] + q1);
                *(uint32_t*)((uint16_t*)g_Qb + (m0 + qrow + 8) * KP + c) =
                    pack2(acc[t][2] + q0, acc[t][3] + q1);
            }
        }
    }
}

// ---------------- main: register-chained mma + work stealing + fused finish -------
__global__ void __launch_bounds__(NTH, 1)
umnn_main(const float* __restrict__ x,
          const float* __restrict__ U2, const float* __restrict__ c2,
          const float* __restrict__ U3, const float* __restrict__ c3,
          const float* __restrict__ U4, const float* __restrict__ c4,
          float* __restrict__ out)
{
    extern __shared__ __align__(16) uint16_t Wsm[];
    __shared__ unsigned int slast;
    int tid = threadIdx.x;

    for (int i = tid; i < KP * W23_LD; i += NTH) {
        int k = i / W23_LD, n = i - k * W23_LD;
        float a = 0.f, b = 0.f;
        if (k < HU && n < HU) {
            a = __ldg(U2 + k * HU + n);
            b = __ldg(U3 + k * HU + n);
        } else if (k == BIAS_K) {
            if (n < HU)            { a = __ldg(c2 + n); b = __ldg(c3 + n); }
            else if (n == BIAS_K)  { a = 1.0f;          b = 1.0f; }
        }
        __nv_bfloat16 ha = __float2bfloat16(a), hb = __float2bfloat16(b);
        Wsm[W2_OFF + i] = *(uint16_t*)&ha;
        Wsm[W3_OFF + i] = *(uint16_t*)&hb;
    }
    for (int i = tid; i < KP * W4_LD; i += NTH) {
        int k = i / W4_LD, n = i - k * W4_LD;
        float a = 0.f;
        if (k < HU && n < D_SZ)            a = __ldg(U4 + k * D_SZ + n);
        else if (k == BIAS_K && n < D_SZ)  a = __ldg(c4 + n);
        __nv_bfloat16 ha = __float2bfloat16(a);
        Wsm[W4_OFF + i] = *(uint16_t*)&ha;
    }
    __syncthreads();

    const uint16_t* W2s = Wsm + W2_OFF;
    const uint16_t* W3s = Wsm + W3_OFF;
    const uint16_t* W4s = Wsm + W4_OFF;

    int lane = tid & 31;
    int tg = lane & 3, qrow = lane >> 2;
    int l16 = lane & 15, lh = lane >> 4;

    for (;;) {
        // work-stealing: lane 0 grabs the next 16-row chunk
        unsigned int chunk;
        if (lane == 0) chunk = atomicAdd(&g_work, 1u);
        chunk = __shfl_sync(0xffffffff, chunk, 0);
        if (chunk >= NCHUNK) break;

        int r0 = (int)chunk * 16;
        int rA = r0 + qrow, rB = rA + 8;
        int bA = rA / T_STEPS, bB = rB / T_STEPS;
        float tA = ((float)(rA - bA * T_STEPS) + 0.5f) * (1.0f / T_STEPS);
        float tB = ((float)(rB - bB * T_STEPS) + 0.5f) * (1.0f / T_STEPS);
        const uint16_t* PA = (const uint16_t*)g_Pb + bA * KP;
        const uint16_t* QA = (const uint16_t*)g_Qb + bA * KP;
        const uint16_t* PB = (const uint16_t*)g_Pb + bB * KP;
        const uint16_t* QB = (const uint16_t*)g_Qb + bB * KP;

        uint32_t af[7][4];
        #pragma unroll
        for (int j = 0; j < 7; j++) {
            int k0 = j * 16 + tg * 2;
            af[j][0] = bpair(PA, QA, k0,     tA);
            af[j][1] = bpair(PB, QB, k0,     tB);
            af[j][2] = bpair(PA, QA, k0 + 8, tA);
            af[j][3] = bpair(PB, QB, k0 + 8, tB);
        }

        float acc[13][4];
        gemm_chain13<W23_LD>(af, W2s, l16, lh, acc);
        repack13(acc, af);
        gemm_chain13<W23_LD>(af, W3s, l16, lh, acc);
        repack13(acc, af);

        float acc4[16][4];
        gemm_chain16<W4_LD>(af, W4s, l16, lh, acc4);

        const float* xA = x + bA * D_SZ;
        const float* xB = x + bB * D_SZ;
        float sA = 0.f, sB = 0.f;
        #pragma unroll
        for (int nt = 0; nt < 16; nt++) {
            int c = nt * 8 + tg * 2;
            float p0 = acc4[nt][0], p1 = acc4[nt][1];
            float p2 = acc4[nt][2], p3 = acc4[nt][3];
            float f0 = p0 > 0.f ? p0 + 1.f : __expf(p0);
            float f1 = p1 > 0.f ? p1 + 1.f : __expf(p1);
            float f2 = p2 > 0.f ? p2 + 1.f : __expf(p2);
            float f3 = p3 > 0.f ? p3 + 1.f : __expf(p3);
            sA += f0 * __ldg(xA + c) + f1 * __ldg(xA + c + 1);
            sB += f2 * __ldg(xB + c) + f3 * __ldg(xB + c + 1);
        }
        sA += __shfl_xor_sync(0xffffffff, sA, 1);
        sA += __shfl_xor_sync(0xffffffff, sA, 2);
        sB += __shfl_xor_sync(0xffffffff, sB, 1);
        sB += __shfl_xor_sync(0xffffffff, sB, 2);
        if (tg == 0) {
            atomicAdd(&g_F[bA], sA);
            atomicAdd(&g_F[bB], sB);
        }
    }

    // fused finish: last CTA to retire computes sigmoid(F/300) -> out
    __syncthreads();
    if (tid == 0) {
        __threadfence();
        unsigned int o = atomicAdd(&g_done, 1u);
        slast = (o == GRID - 1u) ? 1u : 0u;
    }
    __syncthreads();
    if (slast) {
        __threadfence();
        for (int i = tid; i < B_SZ; i += NTH) {
            float F = g_F[i] * (1.0f / T_STEPS);
            out[i] = 1.0f / (1.0f + expf(-F));
        }
    }
}

// ---------------- launch ----------------
extern "C" void kernel_launch(void* const* d_in, const int* in_sizes, int n_in,
                              void* d_out, int out_size)
{
    (void)in_sizes; (void)n_in; (void)out_size;
    const float* x  = (const float*)d_in[0];
    const float* W1 = (const float*)d_in[1];
    const float* b1 = (const float*)d_in[2];
    const float* W2 = (const float*)d_in[3];
    const float* b2 = (const float*)d_in[4];
    const float* W3 = (const float*)d_in[5];
    const float* b3 = (const float*)d_in[6];
    const float* U1 = (const float*)d_in[7];
    const float* c1 = (const float*)d_in[8];
    const float* U2 = (const float*)d_in[9];
    const float* c2 = (const float*)d_in[10];
    const float* U3 = (const float*)d_in[11];
    const float* c3 = (const float*)d_in[12];
    const float* U4 = (const float*)d_in[13];
    const float* c4 = (const float*)d_in[14];
    float* out = (float*)d_out;

    cudaFuncSetAttribute(umnn_main, cudaFuncAttributeMaxDynamicSharedMemorySize, SMEM_MAIN);
    cudaFuncSetAttribute(prep_tensor, cudaFuncAttributeMaxDynamicSharedMemorySize, PREP_SMEM);

    // 1) pack prep weights + zero F + reset tickets
    pack_prep<<<dim3(176, 6), 256>>>(W1, W2, W3, U1);
    // 2) tensor-core prep (256 threads/CTA)
    prep_tensor<<<B_SZ / 16, PTH, PREP_SMEM>>>(x, b1, b2, b3, c1);
    // 3) register-chained persistent mma main kernel (work stealing + fused finish)
    umnn_main<<<GRID, NTH, SMEM_MAIN>>>(x, U2, c2, U3, c3, U4, c4, out);
}

// round 17
// speedup vs baseline: 1.3686x; 1.3686x over previous
#include <cuda_runtime.h>
#include <cuda_bf16.h>
#include <cstdint>

// ---------------- problem constants ----------------
#define B_SZ     2048
#define D_SZ     128
#define C_SZ     64
#define T_STEPS  300
#define HU       100
#define ROWS_TOTAL (B_SZ * T_STEPS)       // 614400
#define GRID     148
#define NTH      512
#define NCHUNK   (ROWS_TOTAL / 16)        // 38400
#define GW_STRIDE (GRID * 16)

#define KP      112                        // padded hidden; col/row 100 = bias lane
#define BIAS_K  100
#define W23_LD  120
#define W4_LD   136
#define W2_OFF  0
#define W3_OFF  (KP * W23_LD)
#define W4_OFF  (2 * KP * W23_LD)
#define W_TOTAL (2 * KP * W23_LD + KP * W4_LD)   // 42112 b16
#define SMEM_MAIN (W_TOTAL * 2)                  // 84224 B

// prep packed-weight layouts (bf16, [k][LD])
#define PBLD   216
#define P3LD   72
#define PULD   120
#define W1P_N  (128 * PBLD)
#define W2P_N  (208 * PBLD)
#define W3P_N  (208 * P3LD)
#define U1PP_N (128 * PULD)
#define U1QP_N (64 * PULD)
#define PREP_SMEM ((W2P_N + 2 * 16 * PBLD) * 2)
#define PTH    256

// ---------------- device globals ----------------
__device__ __align__(16) __nv_bfloat16 g_Pb[B_SZ * KP];
__device__ __align__(16) __nv_bfloat16 g_Qb[B_SZ * KP];
__device__ float g_F[B_SZ];
__device__ unsigned int g_done;
__device__ __align__(16) uint16_t g_W1p[W1P_N];
__device__ __align__(16) uint16_t g_W2p[W2P_N];
__device__ __align__(16) uint16_t g_W3p[W3P_N];
__device__ __align__(16) uint16_t g_U1Pp[U1PP_N];
__device__ __align__(16) uint16_t g_U1Qp[U1QP_N];

// ---------------- helpers ----------------
__device__ __forceinline__ uint32_t smem_u32(const void* p) {
    return (uint32_t)__cvta_generic_to_shared(p);
}
__device__ __forceinline__ void ldm_x4_t(uint32_t addr, uint32_t& r0, uint32_t& r1,
                                         uint32_t& r2, uint32_t& r3) {
    asm volatile("ldmatrix.sync.aligned.m8n8.x4.trans.shared.b16 {%0,%1,%2,%3}, [%4];"
                 : "=r"(r0), "=r"(r1), "=r"(r2), "=r"(r3) : "r"(addr));
}
__device__ __forceinline__ void mma_bf16(float c[4], uint32_t a0, uint32_t a1, uint32_t a2,
                                         uint32_t a3, uint32_t b0, uint32_t b1) {
    asm volatile(
        "mma.sync.aligned.m16n8k16.row.col.f32.bf16.bf16.f32 "
        "{%0,%1,%2,%3},{%4,%5,%6,%7},{%8,%9},{%0,%1,%2,%3};"
        : "+f"(c[0]), "+f"(c[1]), "+f"(c[2]), "+f"(c[3])
        : "r"(a0), "r"(a1), "r"(a2), "r"(a3), "r"(b0), "r"(b1));
}
__device__ __forceinline__ uint32_t pack_relu2(float v0, float v1) {
    __nv_bfloat162 h = __floats2bfloat162_rn(fmaxf(v0, 0.f), fmaxf(v1, 0.f));
    return *(uint32_t*)&h;
}
__device__ __forceinline__ uint32_t pack2(float v0, float v1) {
    __nv_bfloat162 h = __floats2bfloat162_rn(v0, v1);
    return *(uint32_t*)&h;
}
__device__ __forceinline__ uint32_t bpair(const uint16_t* P, const uint16_t* Q,
                                          int k, float tv) {
    uint32_t pu = __ldg((const uint32_t*)(P + k));
    uint32_t qu = __ldg((const uint32_t*)(Q + k));
    float2 p2 = __bfloat1622float2(*(__nv_bfloat162*)&pu);
    float2 q2 = __bfloat1622float2(*(__nv_bfloat162*)&qu);
    return pack2(fmaxf(fmaf(tv, p2.x, q2.x), 0.f), fmaxf(fmaf(tv, p2.y, q2.y), 0.f));
}

// 13-tile chained GEMM (cols 0..103): 6 full tile-pairs + half pair (acc[12] only).
template<int BLD>
__device__ __forceinline__ void gemm_chain13(const uint32_t af[7][4], const uint16_t* wS,
                                             int l16, int lh, float acc[13][4])
{
    #pragma unroll
    for (int nt = 0; nt < 13; nt++)
        #pragma unroll
        for (int i = 0; i < 4; i++) acc[nt][i] = 0.f;
    #pragma unroll
    for (int kk = 0; kk < 7; kk++) {
        const uint16_t* wrow = wS + (kk * 16 + l16) * BLD + 8 * lh;
        #pragma unroll
        for (int np = 0; np < 6; np++) {
            uint32_t r0, r1, r2, r3;
            ldm_x4_t(smem_u32(wrow + np * 16), r0, r1, r2, r3);
            mma_bf16(acc[2 * np],     af[kk][0], af[kk][1], af[kk][2], af[kk][3], r0, r1);
            mma_bf16(acc[2 * np + 1], af[kk][0], af[kk][1], af[kk][2], af[kk][3], r2, r3);
        }
        {
            uint32_t r0, r1, r2, r3;
            ldm_x4_t(smem_u32(wrow + 6 * 16), r0, r1, r2, r3);
            mma_bf16(acc[12], af[kk][0], af[kk][1], af[kk][2], af[kk][3], r0, r1);
        }
    }
}
template<int BLD>
__device__ __forceinline__ void gemm_chain16(const uint32_t af[7][4], const uint16_t* wS,
                                             int l16, int lh, float acc[16][4])
{
    #pragma unroll
    for (int nt = 0; nt < 16; nt++)
        #pragma unroll
        for (int i = 0; i < 4; i++) acc[nt][i] = 0.f;
    #pragma unroll
    for (int kk = 0; kk < 7; kk++) {
        const uint16_t* wrow = wS + (kk * 16 + l16) * BLD + 8 * lh;
        #pragma unroll
        for (int np = 0; np < 8; np++) {
            uint32_t r0, r1, r2, r3;
            ldm_x4_t(smem_u32(wrow + np * 16), r0, r1, r2, r3);
            mma_bf16(acc[2 * np],     af[kk][0], af[kk][1], af[kk][2], af[kk][3], r0, r1);
            mma_bf16(acc[2 * np + 1], af[kk][0], af[kk][1], af[kk][2], af[kk][3], r2, r3);
        }
    }
}
__device__ __forceinline__ void repack13(const float acc[13][4], uint32_t af[7][4])
{
    #pragma unroll
    for (int j = 0; j < 6; j++) {
        af[j][0] = pack_relu2(acc[2 * j][0],     acc[2 * j][1]);
        af[j][1] = pack_relu2(acc[2 * j][2],     acc[2 * j][3]);
        af[j][2] = pack_relu2(acc[2 * j + 1][0], acc[2 * j + 1][1]);
        af[j][3] = pack_relu2(acc[2 * j + 1][2], acc[2 * j + 1][3]);
    }
    af[6][0] = pack_relu2(acc[12][0], acc[12][1]);
    af[6][1] = pack_relu2(acc[12][2], acc[12][3]);
    af[6][2] = 0u;
    af[6][3] = 0u;
}

// ---------------- pack: pad prep weights + zero F + reset ticket ----------------
__global__ void pack_prep(const float* __restrict__ W1, const float* __restrict__ W2,
                          const float* __restrict__ W3, const float* __restrict__ U1)
{
    int i = blockIdx.x * blockDim.x + threadIdx.x;
    int which = blockIdx.y;
    if (which == 0) {
        if (i < W1P_N) {
            int k = i / PBLD, n = i - k * PBLD;
            float v = (k < 128 && n < 200) ? __ldg(W1 + k * 200 + n) : 0.f;
            __nv_bfloat16 h = __float2bfloat16(v);
            g_W1p[i] = *(uint16_t*)&h;
        }
    } else if (which == 1) {
        if (i < W2P_N) {
            int k = i / PBLD, n = i - k * PBLD;
            float v = (k < 200 && n < 200) ? __ldg(W2 + k * 200 + n) : 0.f;
            __nv_bfloat16 h = __float2bfloat16(v);
            g_W2p[i] = *(uint16_t*)&h;
        }
    } else if (which == 2) {
        if (i < W3P_N) {
            int k = i / P3LD, n = i - k * P3LD;
            float v = (k < 200 && n < C_SZ) ? __ldg(W3 + k * C_SZ + n) : 0.f;
            __nv_bfloat16 h = __float2bfloat16(v);
            g_W3p[i] = *(uint16_t*)&h;
        }
    } else if (which == 3) {
        if (i < U1PP_N) {
            int k = i / PULD, n = i - k * PULD;
            float v = (k < 128 && n < HU) ? __ldg(U1 + k * HU + n) : 0.f;
            __nv_bfloat16 h = __float2bfloat16(v);
            g_U1Pp[i] = *(uint16_t*)&h;
        }
    } else if (which == 4) {
        if (i < U1QP_N) {
            int k = i / PULD, n = i - k * PULD;
            float v = (k < 64 && n < HU) ? __ldg(U1 + (D_SZ + k) * HU + n) : 0.f;
            __nv_bfloat16 h = __float2bfloat16(v);
            g_U1Qp[i] = *(uint16_t*)&h;
        }
    } else {
        if (i < B_SZ) g_F[i] = 0.f;
        if (i == 0) g_done = 0u;
    }
}

// ---------------- prep v8: tensor-core prep, 128 CTAs x 16 rows x 256 thr ---------
__device__ __forceinline__ void cpy16(const uint16_t* g, uint16_t* s, int n16, int tid) {
    const uint4* src = (const uint4*)g;
    uint4* dst = (uint4*)s;
    for (int i = tid; i < n16 / 8; i += PTH) dst[i] = src[i];
}

template<int K16>
__device__ __forceinline__ void layer_mma(const uint32_t af[][4], const uint16_t* wS,
                                          int BLD, int npairs, int nw, int l16, int lh,
                                          int tg, int qrow, const float* bias, int nreal,
                                          uint16_t* outAct, int outLD)
{
    for (int p = nw; p < npairs; p += 8) {
        float acc[2][4] = {};
        #pragma unroll
        for (int kk = 0; kk < K16; kk++) {
            uint32_t r0, r1, r2, r3;
            ldm_x4_t(smem_u32(wS + (kk * 16 + l16) * BLD + p * 16 + 8 * lh),
                     r0, r1, r2, r3);
            mma_bf16(acc[0], af[kk][0], af[kk][1], af[kk][2], af[kk][3], r0, r1);
            mma_bf16(acc[1], af[kk][0], af[kk][1], af[kk][2], af[kk][3], r2, r3);
        }
        #pragma unroll
        for (int t = 0; t < 2; t++) {
            int c = p * 16 + t * 8 + tg * 2;
            float b0 = (c < nreal)     ? __ldg(bias + c)     : 0.f;
            float b1 = (c + 1 < nreal) ? __ldg(bias + c + 1) : 0.f;
            *(uint32_t*)(outAct + qrow * outLD + c) =
                pack_relu2(acc[t][0] + b0, acc[t][1] + b1);
            *(uint32_t*)(outAct + (qrow + 8) * outLD + c) =
                pack_relu2(acc[t][2] + b0, acc[t][3] + b1);
        }
    }
}

template<int K16>
__device__ __forceinline__ void build_af(uint32_t af[][4], const uint16_t* act,
                                         int LD, int tg, int qrow)
{
    #pragma unroll
    for (int j = 0; j < K16; j++) {
        int k0 = j * 16 + tg * 2;
        af[j][0] = *(const uint32_t*)(act + qrow * LD + k0);
        af[j][1] = *(const uint32_t*)(act + (qrow + 8) * LD + k0);
        af[j][2] = *(const uint32_t*)(act + qrow * LD + k0 + 8);
        af[j][3] = *(const uint32_t*)(act + (qrow + 8) * LD + k0 + 8);
    }
}

__global__ void __launch_bounds__(PTH, 1)
prep_tensor(const float* __restrict__ x,
            const float* __restrict__ b1, const float* __restrict__ b2,
            const float* __restrict__ b3, const float* __restrict__ c1)
{
    extern __shared__ __align__(16) uint16_t ps[];
    uint16_t* Wbuf = ps;
    uint16_t* act1 = ps + W2P_N;
    uint16_t* act2 = act1 + 16 * PBLD;

    int tid = threadIdx.x;
    int lane = tid & 31, nw = tid >> 5;      // 8 warps
    int tg = lane & 3, qrow = lane >> 2;
    int l16 = lane & 15, lh = lane >> 4;
    int m0 = blockIdx.x * 16;

    cpy16(g_W1p, Wbuf, W1P_N, tid);
    __syncthreads();

    uint32_t afx[8][4];
    {
        const float* xA = x + (m0 + qrow) * D_SZ;
        const float* xB = xA + 8 * D_SZ;
        #pragma unroll
        for (int j = 0; j < 8; j++) {
            int k0 = j * 16 + tg * 2;
            float2 a0 = *(const float2*)(xA + k0);
            float2 a1 = *(const float2*)(xB + k0);
            float2 a2 = *(const float2*)(xA + k0 + 8);
            float2 a3 = *(const float2*)(xB + k0 + 8);
            afx[j][0] = pack2(a0.x, a0.y);
            afx[j][1] = pack2(a1.x, a1.y);
            afx[j][2] = pack2(a2.x, a2.y);
            afx[j][3] = pack2(a3.x, a3.y);
        }
    }
    layer_mma<8>(afx, Wbuf, PBLD, 13, nw, l16, lh, tg, qrow, b1, 200, act1, PBLD);
    __syncthreads();

    cpy16(g_W2p, Wbuf, W2P_N, tid);
    __syncthreads();
    uint32_t af2[13][4];
    build_af<13>(af2, act1, PBLD, tg, qrow);
    layer_mma<13>(af2, Wbuf, PBLD, 13, nw, l16, lh, tg, qrow, b2, 200, act2, PBLD);
    __syncthreads();

    cpy16(g_W3p,  Wbuf,                  W3P_N,  tid);
    cpy16(g_U1Pp, Wbuf + W3P_N,          U1PP_N, tid);
    cpy16(g_U1Qp, Wbuf + W3P_N + U1PP_N, U1QP_N, tid);
    __syncthreads();

    uint32_t af3[13][4];
    build_af<13>(af3, act2, PBLD, tg, qrow);
    layer_mma<13>(af3, Wbuf, P3LD, 4, nw, l16, lh, tg, qrow, b3, C_SZ, act1, PBLD);

    {
        const uint16_t* Up = Wbuf + W3P_N;
        for (int p = nw; p < 7; p += 8) {
            float acc[2][4] = {};
            #pragma unroll
            for (int kk = 0; kk < 8; kk++) {
                uint32_t r0, r1, r2, r3;
                ldm_x4_t(smem_u32(Up + (kk * 16 + l16) * PULD + p * 16 + 8 * lh),
                         r0, r1, r2, r3);
                mma_bf16(acc[0], afx[kk][0], afx[kk][1], afx[kk][2], afx[kk][3], r0, r1);
                mma_bf16(acc[1], afx[kk][0], afx[kk][1], afx[kk][2], afx[kk][3], r2, r3);
            }
            #pragma unroll
            for (int t = 0; t < 2; t++) {
                int c = p * 16 + t * 8 + tg * 2;
                *(uint32_t*)((uint16_t*)g_Pb + (m0 + qrow) * KP + c) =
                    pack2(acc[t][0], acc[t][1]);
                *(uint32_t*)((uint16_t*)g_Pb + (m0 + qrow + 8) * KP + c) =
                    pack2(acc[t][2], acc[t][3]);
            }
        }
    }
    __syncthreads();

    {
        const uint16_t* Uq = Wbuf + W3P_N + U1PP_N;
        uint32_t afq[4][4];
        build_af<4>(afq, act1, PBLD, tg, qrow);
        for (int p = nw; p < 7; p += 8) {
            float acc[2][4] = {};
            #pragma unroll
            for (int kk = 0; kk < 4; kk++) {
                uint32_t r0, r1, r2, r3;
                ldm_x4_t(smem_u32(Uq + (kk * 16 + l16) * PULD + p * 16 + 8 * lh),
                         r0, r1, r2, r3);
                mma_bf16(acc[0], afq[kk][0], afq[kk][1], afq[kk][2], afq[kk][3], r0, r1);
                mma_bf16(acc[1], afq[kk][0], afq[kk][1], afq[kk][2], afq[kk][3], r2, r3);
            }
            #pragma unroll
            for (int t = 0; t < 2; t++) {
                int c = p * 16 + t * 8 + tg * 2;
                float q0 = (c < HU) ? __ldg(c1 + c)
                                    : ((c == BIAS_K) ? 1.0f : 0.f);
                float q1 = (c + 1 < HU) ? __ldg(c1 + c + 1)
                                        : ((c + 1 == BIAS_K) ? 1.0f : 0.f);
                *(uint32_t*)((uint16_t*)g_Qb + (m0 + qrow) * KP + c) =
                    pack2(acc[t][0] + q0, acc[t][1] + q1);
                *(uint32_t*)((uint16_t*)g_Qb + (m0 + qrow + 8) * KP + c) =
                    pack2(acc[t][2] + q0, acc[t][3] + q1);
            }
        }
    }
}

// ---------------- main: register-chained mma, static grid-stride (R15) ------------
__global__ void __launch_bounds__(NTH, 1)
umnn_main(const float* __restrict__ x,
          const float* __restrict__ U2, const float* __restrict__ c2,
          const float* __restrict__ U3, const float* __restrict__ c3,
          const float* __restrict__ U4, const float* __restrict__ c4,
          float* __restrict__ out)
{
    extern __shared__ __align__(16) uint16_t Wsm[];
    __shared__ unsigned int slast;
    int tid = threadIdx.x;

    for (int i = tid; i < KP * W23_LD; i += NTH) {
        int k = i / W23_LD, n = i - k * W23_LD;
        float a = 0.f, b = 0.f;
        if (k < HU && n < HU) {
            a = __ldg(U2 + k * HU + n);
            b = __ldg(U3 + k * HU + n);
        } else if (k == BIAS_K) {
            if (n < HU)            { a = __ldg(c2 + n); b = __ldg(c3 + n); }
            else if (n == BIAS_K)  { a = 1.0f;          b = 1.0f; }
        }
        __nv_bfloat16 ha = __float2bfloat16(a), hb = __float2bfloat16(b);
        Wsm[W2_OFF + i] = *(uint16_t*)&ha;
        Wsm[W3_OFF + i] = *(uint16_t*)&hb;
    }
    for (int i = tid; i < KP * W4_LD; i += NTH) {
        int k = i / W4_LD, n = i - k * W4_LD;
        float a = 0.f;
        if (k < HU && n < D_SZ)            a = __ldg(U4 + k * D_SZ + n);
        else if (k == BIAS_K && n < D_SZ)  a = __ldg(c4 + n);
        __nv_bfloat16 ha = __float2bfloat16(a);
        Wsm[W4_OFF + i] = *(uint16_t*)&ha;
    }
    __syncthreads();

    const uint16_t* W2s = Wsm + W2_OFF;
    const uint16_t* W3s = Wsm + W3_OFF;
    const uint16_t* W4s = Wsm + W4_OFF;

    int lane = tid & 31, w = tid >> 5;
    int tg = lane & 3, qrow = lane >> 2;
    int l16 = lane & 15, lh = lane >> 4;
    int gw = blockIdx.x * 16 + w;

    for (int chunk = gw; chunk < NCHUNK; chunk += GW_STRIDE) {
        int r0 = chunk * 16;
        int rA = r0 + qrow, rB = rA + 8;
        int bA = rA / T_STEPS, bB = rB / T_STEPS;
        float tA = ((float)(rA - bA * T_STEPS) + 0.5f) * (1.0f / T_STEPS);
        float tB = ((float)(rB - bB * T_STEPS) + 0.5f) * (1.0f / T_STEPS);
        const uint16_t* PA = (const uint16_t*)g_Pb + bA * KP;
        const uint16_t* QA = (const uint16_t*)g_Qb + bA * KP;
        const uint16_t* PB = (const uint16_t*)g_Pb + bB * KP;
        const uint16_t* QB = (const uint16_t*)g_Qb + bB * KP;

        uint32_t af[7][4];
        #pragma unroll
        for (int j = 0; j < 7; j++) {
            int k0 = j * 16 + tg * 2;
            af[j][0] = bpair(PA, QA, k0,     tA);
            af[j][1] = bpair(PB, QB, k0,     tB);
            af[j][2] = bpair(PA, QA, k0 + 8, tA);
            af[j][3] = bpair(PB, QB, k0 + 8, tB);
        }

        float acc[13][4];
        gemm_chain13<W23_LD>(af, W2s, l16, lh, acc);
        repack13(acc, af);
        gemm_chain13<W23_LD>(af, W3s, l16, lh, acc);
        repack13(acc, af);

        float acc4[16][4];
        gemm_chain16<W4_LD>(af, W4s, l16, lh, acc4);

        const float* xA = x + bA * D_SZ;
        const float* xB = x + bB * D_SZ;
        float sA = 0.f, sB = 0.f;
        #pragma unroll
        for (int nt = 0; nt < 16; nt++) {
            int c = nt * 8 + tg * 2;
            float p0 = acc4[nt][0], p1 = acc4[nt][1];
            float p2 = acc4[nt][2], p3 = acc4[nt][3];
            float f0 = p0 > 0.f ? p0 + 1.f : __expf(p0);
            float f1 = p1 > 0.f ? p1 + 1.f : __expf(p1);
            float f2 = p2 > 0.f ? p2 + 1.f : __expf(p2);
            float f3 = p3 > 0.f ? p3 + 1.f : __expf(p3);
            sA += f0 * __ldg(xA + c) + f1 * __ldg(xA + c + 1);
            sB += f2 * __ldg(xB + c) + f3 * __ldg(xB + c + 1);
        }
        sA += __shfl_xor_sync(0xffffffff, sA, 1);
        sA += __shfl_xor_sync(0xffffffff, sA, 2);
        sB += __shfl_xor_sync(0xffffffff, sB, 1);
        sB += __shfl_xor_sync(0xffffffff, sB, 2);
        if (tg == 0) {
            atomicAdd(&g_F[bA], sA);
            atomicAdd(&g_F[bB], sB);
        }
    }

    // fused finish: last CTA to retire computes sigmoid(F/300) -> out
    __syncthreads();
    if (tid == 0) {
        __threadfence();
        unsigned int o = atomicAdd(&g_done, 1u);
        slast = (o == GRID - 1u) ? 1u : 0u;
    }
    __syncthreads();
    if (slast) {
        __threadfence();
        for (int i = tid; i < B_SZ; i += NTH) {
            float F = g_F[i] * (1.0f / T_STEPS);
            out[i] = 1.0f / (1.0f + expf(-F));
        }
    }
}

// ---------------- launch ----------------
extern "C" void kernel_launch(void* const* d_in, const int* in_sizes, int n_in,
                              void* d_out, int out_size)
{
    (void)in_sizes; (void)n_in; (void)out_size;
    const float* x  = (const float*)d_in[0];
    const float* W1 = (const float*)d_in[1];
    const float* b1 = (const float*)d_in[2];
    const float* W2 = (const float*)d_in[3];
    const float* b2 = (const float*)d_in[4];
    const float* W3 = (const float*)d_in[5];
    const float* b3 = (const float*)d_in[6];
    const float* U1 = (const float*)d_in[7];
    const float* c1 = (const float*)d_in[8];
    const float* U2 = (const float*)d_in[9];
    const float* c2 = (const float*)d_in[10];
    const float* U3 = (const float*)d_in[11];
    const float* c3 = (const float*)d_in[12];
    const float* U4 = (const float*)d_in[13];
    const float* c4 = (const float*)d_in[14];
    float* out = (float*)d_out;

    cudaFuncSetAttribute(umnn_main, cudaFuncAttributeMaxDynamicSharedMemorySize, SMEM_MAIN);
    cudaFuncSetAttribute(prep_tensor, cudaFuncAttributeMaxDynamicSharedMemorySize, PREP_SMEM);

    // 1) pack prep weights + zero F + reset ticket
    pack_prep<<<dim3(176, 6), 256>>>(W1, W2, W3, U1);
    // 2) tensor-core prep (256 threads/CTA)
    prep_tensor<<<B_SZ / 16, PTH, PREP_SMEM>>>(x, b1, b2, b3, c1);
    // 3) register-chained persistent mma main kernel (static grid-stride, fused finish)
    umnn_main<<<GRID, NTH, SMEM_MAIN>>>(x, U2, c2, U3, c3, U4, c4, out);
}